// round 5
// baseline (speedup 1.0000x reference)
#include <cuda_runtime.h>
#include <cuda_fp16.h>
#include <math.h>

#define NMAX 50048
#define EMAX 800000
#define SCAN_B 256

// ---------------- scratch (device globals) ----------------
__device__ __half2 g_h[NMAX * 64];     // x @ W_gat  (fp16 messages)
__device__ __half2 g_h2[NMAX * 64];    // out1 @ W_gcn (fp16 messages)
__device__ float g_asrc[NMAX * 4];
__device__ float g_adst[NMAX * 4];
__device__ float g_out1[NMAX * 128];
__device__ float g_out2[NMAX * 128];
__device__ float g_gate[NMAX];
__device__ float g_dinv[NMAX];
__device__ int   g_cnt[NMAX];
__device__ int   g_offs[NMAX + 1];
__device__ int   g_cursor[NMAX];
__device__ int   g_csr[EMAX];
__device__ int   g_bsum[(NMAX + SCAN_B - 1) / SCAN_B];
__device__ int   g_boff[(NMAX + SCAN_B - 1) / SCAN_B];
__device__ int   g_gstart[64];
__device__ int   g_gend[64];

// ---------------- helpers ----------------
__device__ __forceinline__ float lrelu(float v) { return v > 0.f ? v : 0.2f * v; }
__device__ __forceinline__ float elu_f(float v) { return v > 0.f ? v : (__expf(v) - 1.f); }
__device__ __forceinline__ float getc(float4 v, int i) {
    return i == 0 ? v.x : i == 1 ? v.y : i == 2 ? v.z : v.w;
}
__device__ __forceinline__ void ffma2(unsigned long long& d, unsigned long long a,
                                      unsigned long long b) {
    asm("fma.rn.f32x2 %0, %1, %2, %0;" : "+l"(d) : "l"(a), "l"(b));
}
__device__ __forceinline__ unsigned long long dup2(float v) {
    unsigned long long r;
    asm("mov.b64 %0, {%1, %1};" : "=l"(r) : "f"(v));
    return r;
}

// ---------------- init ----------------
__global__ void init_kernel(int* cnt, int* gs, int* ge, int N) {
    int i = blockIdx.x * blockDim.x + threadIdx.x;
    if (i < N) cnt[i] = 0;
    if (i < 64) { gs[i] = 0; ge[i] = 0; }
}

// ---------------- GEMM: Ch[N,128](fp16) = A[N,128] @ W[128,128] (+ optional attn epilogue) ----------------
template <bool ATTN>
__global__ __launch_bounds__(256) void gemm128_kernel(const float* __restrict__ A,
                                                      const float* __restrict__ W,
                                                      __half2* __restrict__ Ch,
                                                      const float* __restrict__ att_src,
                                                      const float* __restrict__ att_dst,
                                                      float* __restrict__ asrc,
                                                      float* __restrict__ adst, int N) {
    __shared__ float Ws[32 * 128];
    int t  = threadIdx.x;
    int cg = t & 7;
    int rq = t >> 3;
    int row0 = blockIdx.x * 128 + rq * 4;

    unsigned long long acc[4][8];
    #pragma unroll
    for (int j = 0; j < 4; j++)
        #pragma unroll
        for (int i = 0; i < 8; i++) acc[j][i] = 0ull;

    #pragma unroll
    for (int kk = 0; kk < 128; kk += 32) {
        __syncthreads();
        #pragma unroll
        for (int i = t; i < 1024; i += 256)
            ((float4*)Ws)[i] = ((const float4*)W)[kk * 32 + i];
        __syncthreads();

        #pragma unroll
        for (int k4 = 0; k4 < 8; k4++) {
            float4 a[4];
            #pragma unroll
            for (int j = 0; j < 4; j++) {
                int row = row0 + j;
                a[j] = (row < N) ? ((const float4*)A)[row * 32 + (kk >> 2) + k4]
                                 : make_float4(0.f, 0.f, 0.f, 0.f);
            }
            #pragma unroll
            for (int u = 0; u < 4; u++) {
                const float* wr = Ws + (k4 * 4 + u) * 128 + cg * 16;
                ulonglong2 w0 = *(const ulonglong2*)(wr);
                ulonglong2 w1 = *(const ulonglong2*)(wr + 4);
                ulonglong2 w2 = *(const ulonglong2*)(wr + 8);
                ulonglong2 w3 = *(const ulonglong2*)(wr + 12);
                #pragma unroll
                for (int j = 0; j < 4; j++) {
                    unsigned long long av2 = dup2(getc(a[j], u));
                    ffma2(acc[j][0], av2, w0.x); ffma2(acc[j][1], av2, w0.y);
                    ffma2(acc[j][2], av2, w1.x); ffma2(acc[j][3], av2, w1.y);
                    ffma2(acc[j][4], av2, w2.x); ffma2(acc[j][5], av2, w2.y);
                    ffma2(acc[j][6], av2, w3.x); ffma2(acc[j][7], av2, w3.y);
                }
            }
        }
    }

    float cf[4][16];
    #pragma unroll
    for (int j = 0; j < 4; j++)
        #pragma unroll
        for (int m = 0; m < 4; m++) {
            float2 lo = *(float2*)&acc[j][2 * m];
            float2 hi = *(float2*)&acc[j][2 * m + 1];
            cf[j][m * 4 + 0] = lo.x; cf[j][m * 4 + 1] = lo.y;
            cf[j][m * 4 + 2] = hi.x; cf[j][m * 4 + 3] = hi.y;
        }

    // fp16 output: 16 cols -> 8 half2 -> two uint4 stores
    #pragma unroll
    for (int j = 0; j < 4; j++) {
        int row = row0 + j;
        if (row < N) {
            __half2 hh[8];
            #pragma unroll
            for (int m = 0; m < 8; m++)
                hh[m] = __float22half2_rn(make_float2(cf[j][2 * m], cf[j][2 * m + 1]));
            uint4* cp = (uint4*)(Ch + row * 64 + cg * 8);
            cp[0] = *(uint4*)&hh[0];
            cp[1] = *(uint4*)&hh[4];
        }
    }

    if (ATTN) {
        int hg = cg >> 1;
        const float* as_p = att_src + hg * 32 + (cg & 1) * 16;
        const float* ad_p = att_dst + hg * 32 + (cg & 1) * 16;
        float av[16], dv[16];
        #pragma unroll
        for (int k = 0; k < 16; k++) { av[k] = as_p[k]; dv[k] = ad_p[k]; }
        #pragma unroll
        for (int j = 0; j < 4; j++) {
            float ps = 0.f, pd = 0.f;
            #pragma unroll
            for (int k = 0; k < 16; k++) { ps += cf[j][k] * av[k]; pd += cf[j][k] * dv[k]; }
            ps += __shfl_xor_sync(0xffffffffu, ps, 1);
            pd += __shfl_xor_sync(0xffffffffu, pd, 1);
            int row = row0 + j;
            if (!(cg & 1) && row < N) {
                asrc[row * 4 + hg] = ps;
                adst[row * 4 + hg] = pd;
            }
        }
    }
}

// ---------------- CSR build ----------------
__global__ void hist_kernel(const int* __restrict__ ei, int E, int* cnt) {
    int e = blockIdx.x * blockDim.x + threadIdx.x;
    if (e >= E) return;
    atomicAdd(cnt + ei[E + e], 1);
}

__global__ __launch_bounds__(SCAN_B) void blocksum_kernel(const int* __restrict__ cnt,
                                                          int* bsum, int N) {
    __shared__ int sh[SCAN_B];
    int i = blockIdx.x * SCAN_B + threadIdx.x;
    sh[threadIdx.x] = (i < N) ? cnt[i] : 0;
    __syncthreads();
    #pragma unroll
    for (int o = SCAN_B / 2; o; o >>= 1) {
        if (threadIdx.x < o) sh[threadIdx.x] += sh[threadIdx.x + o];
        __syncthreads();
    }
    if (threadIdx.x == 0) bsum[blockIdx.x] = sh[0];
}

__global__ __launch_bounds__(256) void bscan_kernel(const int* __restrict__ bsum,
                                                    int* boff, int NB) {
    __shared__ int sh[256];
    int t = threadIdx.x;
    sh[t] = (t < NB) ? bsum[t] : 0;
    __syncthreads();
    #pragma unroll
    for (int o = 1; o < 256; o <<= 1) {
        int v = (t >= o) ? sh[t - o] : 0;
        __syncthreads();
        sh[t] += v;
        __syncthreads();
    }
    if (t < NB) boff[t] = (t == 0) ? 0 : sh[t - 1];
}

__global__ __launch_bounds__(SCAN_B) void scanfin_kernel(const int* __restrict__ cnt,
                                                         const int* __restrict__ boff,
                                                         int* offs, int* cursor, int N, int E) {
    __shared__ int sh[SCAN_B];
    int t = threadIdx.x;
    int i = blockIdx.x * SCAN_B + t;
    int v = (i < N) ? cnt[i] : 0;
    sh[t] = v;
    __syncthreads();
    #pragma unroll
    for (int o = 1; o < SCAN_B; o <<= 1) {
        int u = (t >= o) ? sh[t - o] : 0;
        __syncthreads();
        sh[t] += u;
        __syncthreads();
    }
    if (i < N) {
        int off = boff[blockIdx.x] + sh[t] - v;
        offs[i] = off;
        cursor[i] = off;
    }
    if (i == 0) offs[N] = E;
}

__global__ void scatter_kernel(const int* __restrict__ ei, int E, int* cursor, int* csr) {
    int e = blockIdx.x * blockDim.x + threadIdx.x;
    if (e >= E) return;
    int d = ei[E + e];
    int pos = atomicAdd(cursor + d, 1);
    csr[pos] = ei[e];
}

// ---------------- graph boundaries ----------------
__global__ void bounds_kernel(const int* __restrict__ batch, int* gs, int* ge, int N) {
    int n = blockIdx.x * blockDim.x + threadIdx.x;
    if (n >= N) return;
    int b = batch[n];
    if (n == 0 || batch[n - 1] != b) gs[b] = n;
    if (n == N - 1 || batch[n + 1] != b) ge[b] = n + 1;
}

// ---------------- GAT aggregation: warp/node, pipelined, fully-unrolled broadcasts ----------------
__global__ __launch_bounds__(256) void gat_agg_kernel(const int* __restrict__ csr,
                                                      const int* __restrict__ offs,
                                                      const __half2* __restrict__ h,
                                                      const float* __restrict__ asrc,
                                                      const float* __restrict__ adst,
                                                      const float* __restrict__ b_gat,
                                                      const float* __restrict__ bn1w,
                                                      const float* __restrict__ bn1b,
                                                      float* __restrict__ out1,
                                                      float* __restrict__ dinv, int N) {
    int n = (blockIdx.x * 256 + threadIdx.x) >> 5;
    if (n >= N) return;
    int lane = threadIdx.x & 31;
    int hd  = lane >> 3;
    int sub = lane & 7;
    int grp = lane & 24;
    int beg = offs[n], end = offs[n + 1];

    float adn = __ldg(adst + n * 4 + hd);
    float asn = __ldg(asrc + n * 4 + hd);
    float wself = __expf(lrelu(asn + adn));

    // self contribution (fp16 row -> fp32)
    float2 h0 = __half22float2(__ldg(h + n * 64 + lane * 2));
    float2 h1 = __half22float2(__ldg(h + n * 64 + lane * 2 + 1));
    float4 acc = make_float4(h0.x * wself, h0.y * wself, h1.x * wself, h1.y * wself);

    // prefetch first chunk
    int s_nxt = 0; float w_nxt = 0.f;
    {
        int e = beg + sub;
        if (e < end) {
            s_nxt = __ldg(csr + e);
            w_nxt = __expf(lrelu(__ldg(asrc + s_nxt * 4 + hd) + adn));
        }
    }
    float wpart = w_nxt;

    for (int c0 = beg; c0 < end; c0 += 8) {
        int s_cur = s_nxt; float w_cur = w_nxt;
        int e = c0 + 8 + sub;
        s_nxt = 0; w_nxt = 0.f;
        if (e < end) {
            s_nxt = __ldg(csr + e);
            w_nxt = __expf(lrelu(__ldg(asrc + s_nxt * 4 + hd) + adn));
        }
        wpart += w_nxt;
        #pragma unroll
        for (int i = 0; i < 8; i++) {
            int   si = __shfl_sync(0xffffffffu, s_cur, i);
            float a  = __shfl_sync(0xffffffffu, w_cur, grp + i);
            float2 g0 = __half22float2(__ldg(h + si * 64 + lane * 2));
            float2 g1 = __half22float2(__ldg(h + si * 64 + lane * 2 + 1));
            acc.x += g0.x * a; acc.y += g0.y * a;
            acc.z += g1.x * a; acc.w += g1.y * a;
        }
    }

    #pragma unroll
    for (int o = 1; o < 8; o <<= 1) wpart += __shfl_xor_sync(0xffffffffu, wpart, o);
    float inv = 1.f / (wpart + wself + 1e-16f);

    int c = lane * 4;
    float4 bb = *(const float4*)(b_gat + c);
    float4 w1 = *(const float4*)(bn1w + c);
    float4 b1 = *(const float4*)(bn1b + c);
    float4 v;
    v.x = elu_f(acc.x * inv + bb.x) * w1.x + b1.x;
    v.y = elu_f(acc.y * inv + bb.y) * w1.y + b1.y;
    v.z = elu_f(acc.z * inv + bb.z) * w1.z + b1.z;
    v.w = elu_f(acc.w * inv + bb.w) * w1.w + b1.w;
    *(float4*)(out1 + n * 128 + c) = v;

    if (lane == 0) dinv[n] = rsqrtf((float)(end - beg + 1));
}

// ---------------- GCN aggregation + gate ----------------
__global__ __launch_bounds__(256) void gcn_agg_kernel(const int* __restrict__ csr,
                                                      const int* __restrict__ offs,
                                                      const __half2* __restrict__ h2,
                                                      const float* __restrict__ dinv,
                                                      const float* __restrict__ b_gcn,
                                                      const float* __restrict__ bn2w,
                                                      const float* __restrict__ bn2b,
                                                      const float* __restrict__ W_gate,
                                                      const float* __restrict__ b_gate,
                                                      float* __restrict__ out2,
                                                      float* __restrict__ gate, int N) {
    int n = (blockIdx.x * 256 + threadIdx.x) >> 5;
    if (n >= N) return;
    int lane = threadIdx.x & 31;
    int sub = lane & 7;
    int beg = offs[n], end = offs[n + 1];
    float dn = __ldg(dinv + n);

    float fs = dn * dn;
    float2 h0 = __half22float2(__ldg(h2 + n * 64 + lane * 2));
    float2 h1 = __half22float2(__ldg(h2 + n * 64 + lane * 2 + 1));
    float4 acc = make_float4(h0.x * fs, h0.y * fs, h1.x * fs, h1.y * fs);

    int s_nxt = 0; float f_nxt = 0.f;
    {
        int e = beg + sub;
        if (e < end) {
            s_nxt = __ldg(csr + e);
            f_nxt = __ldg(dinv + s_nxt) * dn;
        }
    }

    for (int c0 = beg; c0 < end; c0 += 8) {
        int s_cur = s_nxt; float f_cur = f_nxt;
        int e = c0 + 8 + sub;
        s_nxt = 0; f_nxt = 0.f;
        if (e < end) {
            s_nxt = __ldg(csr + e);
            f_nxt = __ldg(dinv + s_nxt) * dn;
        }
        #pragma unroll
        for (int i = 0; i < 8; i++) {
            int   si = __shfl_sync(0xffffffffu, s_cur, i);
            float a  = __shfl_sync(0xffffffffu, f_cur, i);
            float2 g0 = __half22float2(__ldg(h2 + si * 64 + lane * 2));
            float2 g1 = __half22float2(__ldg(h2 + si * 64 + lane * 2 + 1));
            acc.x += g0.x * a; acc.y += g0.y * a;
            acc.z += g1.x * a; acc.w += g1.y * a;
        }
    }

    int c = lane * 4;
    float4 bb = *(const float4*)(b_gcn + c);
    float4 w2 = *(const float4*)(bn2w + c);
    float4 b2 = *(const float4*)(bn2b + c);
    float4 v;
    v.x = elu_f(acc.x + bb.x) * w2.x + b2.x;
    v.y = elu_f(acc.y + bb.y) * w2.y + b2.y;
    v.z = elu_f(acc.z + bb.z) * w2.z + b2.z;
    v.w = elu_f(acc.w + bb.w) * w2.w + b2.w;
    *(float4*)(out2 + n * 128 + c) = v;

    float4 wg = *(const float4*)(W_gate + c);
    float p = v.x * wg.x + v.y * wg.y + v.z * wg.z + v.w * wg.w;
    #pragma unroll
    for (int o = 16; o; o >>= 1) p += __shfl_xor_sync(0xffffffffu, p, o);
    if (lane == 0) gate[n] = p + b_gate[0];
}

// ---------------- pooling + FC ----------------
__global__ __launch_bounds__(256) void pool_kernel(const float* __restrict__ out2,
                                                   const float* __restrict__ gate,
                                                   const int* __restrict__ gs,
                                                   const int* __restrict__ ge,
                                                   const float* __restrict__ W_fc,
                                                   const float* __restrict__ b_fc,
                                                   float* __restrict__ out) {
    int g = blockIdx.x;
    int start = gs[g], end = ge[g];
    int tid = threadIdx.x;
    __shared__ float red[256];
    __shared__ float wsh[256];

    float mx = -3.4e38f;
    for (int n = start + tid; n < end; n += 256) mx = fmaxf(mx, gate[n]);
    red[tid] = mx;
    __syncthreads();
    #pragma unroll
    for (int o = 128; o; o >>= 1) {
        if (tid < o) red[tid] = fmaxf(red[tid], red[tid + o]);
        __syncthreads();
    }
    float gmax = red[0];
    __syncthreads();

    int c = tid & 127, half = tid >> 7;
    float acc = 0.f, wloc = 0.f;
    for (int t0 = start; t0 < end; t0 += 256) {
        int tc = min(256, end - t0);
        if (tid < tc) {
            float wv = __expf(gate[t0 + tid] - gmax);
            wsh[tid] = wv;
            wloc += wv;
        }
        __syncthreads();
        for (int j = half; j < tc; j += 2)
            acc += wsh[j] * out2[(t0 + j) * 128 + c];
        __syncthreads();
    }

    red[tid] = wloc;
    __syncthreads();
    #pragma unroll
    for (int o = 128; o; o >>= 1) {
        if (tid < o) red[tid] += red[tid + o];
        __syncthreads();
    }
    float wsum = red[0];
    __syncthreads();

    red[tid] = acc;
    __syncthreads();
    float val = 0.f;
    if (tid < 128) val = (red[tid] + red[tid + 128]) / (wsum + 1e-16f) * W_fc[tid];
    __syncthreads();
    red[tid] = (tid < 128) ? val : 0.f;
    __syncthreads();
    #pragma unroll
    for (int o = 128; o; o >>= 1) {
        if (tid < o) red[tid] += red[tid + o];
        __syncthreads();
    }
    if (tid == 0) out[g] = red[0] + b_fc[0];
}

// ---------------- launch ----------------
extern "C" void kernel_launch(void* const* d_in, const int* in_sizes, int n_in,
                              void* d_out, int out_size) {
    const float* x       = (const float*)d_in[0];
    const int*   ei      = (const int*)d_in[1];
    const int*   batch   = (const int*)d_in[2];
    const float* W_gat   = (const float*)d_in[3];
    const float* att_src = (const float*)d_in[4];
    const float* att_dst = (const float*)d_in[5];
    const float* b_gat   = (const float*)d_in[6];
    const float* bn1w    = (const float*)d_in[7];
    const float* bn1b    = (const float*)d_in[8];
    const float* W_gcn   = (const float*)d_in[9];
    const float* b_gcn   = (const float*)d_in[10];
    const float* bn2w    = (const float*)d_in[11];
    const float* bn2b    = (const float*)d_in[12];
    const float* W_gate  = (const float*)d_in[13];
    const float* b_gate  = (const float*)d_in[14];
    const float* W_fc    = (const float*)d_in[15];
    const float* b_fc    = (const float*)d_in[16];
    float* out = (float*)d_out;

    int N = in_sizes[0] / 128;
    int E = in_sizes[1] / 2;
    int NB = (N + SCAN_B - 1) / SCAN_B;

    float *p_asrc, *p_adst, *p_out1, *p_out2, *p_gate, *p_dinv;
    __half2 *p_h, *p_h2;
    int *p_cnt, *p_offs, *p_cursor, *p_csr, *p_bsum, *p_boff, *p_gs, *p_ge;
    cudaGetSymbolAddress((void**)&p_h,     g_h);
    cudaGetSymbolAddress((void**)&p_h2,    g_h2);
    cudaGetSymbolAddress((void**)&p_asrc,  g_asrc);
    cudaGetSymbolAddress((void**)&p_adst,  g_adst);
    cudaGetSymbolAddress((void**)&p_out1,  g_out1);
    cudaGetSymbolAddress((void**)&p_out2,  g_out2);
    cudaGetSymbolAddress((void**)&p_gate,  g_gate);
    cudaGetSymbolAddress((void**)&p_dinv,  g_dinv);
    cudaGetSymbolAddress((void**)&p_cnt,   g_cnt);
    cudaGetSymbolAddress((void**)&p_offs,  g_offs);
    cudaGetSymbolAddress((void**)&p_cursor,g_cursor);
    cudaGetSymbolAddress((void**)&p_csr,   g_csr);
    cudaGetSymbolAddress((void**)&p_bsum,  g_bsum);
    cudaGetSymbolAddress((void**)&p_boff,  g_boff);
    cudaGetSymbolAddress((void**)&p_gs,    g_gstart);
    cudaGetSymbolAddress((void**)&p_ge,    g_gend);

    init_kernel<<<(N + 255) / 256, 256>>>(p_cnt, p_gs, p_ge, N);
    bounds_kernel<<<(N + 255) / 256, 256>>>(batch, p_gs, p_ge, N);

    // CSR build (by dst)
    hist_kernel<<<(E + 255) / 256, 256>>>(ei, E, p_cnt);
    blocksum_kernel<<<NB, SCAN_B>>>(p_cnt, p_bsum, N);
    bscan_kernel<<<1, 256>>>(p_bsum, p_boff, NB);
    scanfin_kernel<<<NB, SCAN_B>>>(p_cnt, p_boff, p_offs, p_cursor, N, E);
    scatter_kernel<<<(E + 255) / 256, 256>>>(ei, E, p_cursor, p_csr);

    // GAT
    gemm128_kernel<true><<<(N + 127) / 128, 256>>>(x, W_gat, p_h, att_src, att_dst,
                                                   p_asrc, p_adst, N);
    gat_agg_kernel<<<(N * 32 + 255) / 256, 256>>>(p_csr, p_offs, p_h, p_asrc, p_adst,
                                                  b_gat, bn1w, bn1b, p_out1, p_dinv, N);

    // GCN
    gemm128_kernel<false><<<(N + 127) / 128, 256>>>(p_out1, W_gcn, p_h2,
                                                    nullptr, nullptr, nullptr, nullptr, N);
    gcn_agg_kernel<<<(N * 32 + 255) / 256, 256>>>(p_csr, p_offs, p_h2, p_dinv,
                                                  b_gcn, bn2w, bn2b, W_gate, b_gate,
                                                  p_out2, p_gate, N);

    // pooling + FC
    pool_kernel<<<64, 256>>>(p_out2, p_gate, p_gs, p_ge, W_fc, b_fc, out);
}